// round 1
// baseline (speedup 1.0000x reference)
#include <cuda_runtime.h>
#include <math.h>
#include <stdint.h>

typedef unsigned long long ull;

#define BB 16
#define GG 100
#define AA 21504
#define NA (BB*AA)
#define NBLK1 (NA/256)   // 1344

// ---------------- device scratch (no allocations allowed) ----------------
__device__ float4 g_bbox[NA];          // decoded cx,cy,w,h
__device__ float  g_obj[NA];           // obj logit
__device__ float  g_objc[NA];          // softplus(-obj)
__device__ unsigned char g_fga[NA];    // fg_anchor
__device__ int    g_nmatch[NA];
__device__ int    g_ming[NA];
__device__ double g_part[NBLK1*4];     // per-block partials: sp_sum, obj_fg, iou_loss, fg_cnt

// ---------------- helpers ----------------
__device__ __forceinline__ float min4f(float a,float b,float c,float d){
    return fminf(fminf(a,b),fminf(c,d));
}
__device__ __forceinline__ void anchor_geom(int a, float& xc, float& yc, float& st){
    int off, sh;
    if (a < 16384)      { st = 8.f;  off = 0;     sh = 7; }
    else if (a < 20480) { st = 16.f; off = 16384; sh = 6; }
    else                { st = 32.f; off = 20480; sh = 5; }
    int aa = a - off;
    int iy = aa >> sh, ix = aa & ((1<<sh)-1);
    xc = ((float)ix + 0.5f) * st;
    yc = ((float)iy + 0.5f) * st;
}
__device__ __forceinline__ unsigned fkey(float f){
    unsigned u = __float_as_uint(f);
    return (u & 0x80000000u) ? ~u : (u | 0x80000000u);  // monotone float->uint
}
__device__ __forceinline__ float softplus_f(float x){
    return fmaxf(x, 0.f) + log1pf(expf(-fabsf(x)));
}

// ---------------- K1: decode + obj_cost + fg_anchor + init ----------------
__global__ void k_decode(const float* __restrict__ reg0, const float* __restrict__ obj0,
                         const float* __restrict__ reg1, const float* __restrict__ obj1,
                         const float* __restrict__ reg2, const float* __restrict__ obj2,
                         const float* __restrict__ labels)
{
    int t = blockIdx.x * 256 + threadIdx.x;     // t in [0, NA); block never crosses b
    int b = t / AA, a = t - b * AA;

    __shared__ float sl[GG*5];
    for (int i = threadIdx.x; i < GG*5; i += 256) sl[i] = labels[b*GG*5 + i];
    __syncthreads();

    const float *reg, *obj; int off, sh; float st;
    if (a < 16384)      { reg=reg0; obj=obj0; off=0;     sh=7; st=8.f;  }
    else if (a < 20480) { reg=reg1; obj=obj1; off=16384; sh=6; st=16.f; }
    else                { reg=reg2; obj=obj2; off=20480; sh=5; st=32.f; }
    int aa = a - off, iy = aa >> sh, ix = aa & ((1<<sh)-1);
    int H = 1 << sh, hw = H << sh;

    const float* rb = reg + b*4*hw + iy*H + ix;
    float o0 = rb[0], o1 = rb[hw], o2 = rb[2*hw], o3 = rb[3*hw];
    float ol = obj[b*hw + iy*H + ix];

    float cx = (o0 + (float)ix) * st;
    float cy = (o1 + (float)iy) * st;
    float w  = expf(o2) * st;
    float h  = expf(o3) * st;

    g_bbox[t] = make_float4(cx, cy, w, h);
    g_obj[t]  = ol;
    g_objc[t] = softplus_f(-ol);

    // fg_anchor over ALL 100 gts (invalid gts intentionally included: matches reference)
    float xc = ((float)ix + 0.5f) * st;
    float yc = ((float)iy + 0.5f) * st;
    float r  = 2.5f * st;
    float m = -1e30f;
    #pragma unroll 4
    for (int g = 0; g < GG; g++){
        float gx = sl[g*5+1], gy = sl[g*5+2], gw = sl[g*5+3], gh = sl[g*5+4];
        float ib = min4f(xc-(gx-0.5f*gw), (gx+0.5f*gw)-xc, yc-(gy-0.5f*gh), (gy+0.5f*gh)-yc);
        float ic = min4f(xc-(gx-r), (gx+r)-xc, yc-(gy-r), (gy+r)-yc);
        m = fmaxf(m, fmaxf(ib, ic));
    }
    g_fga[t]    = (m > 0.f) ? 1 : 0;
    g_nmatch[t] = 0;
    g_ming[t]   = 0x7fffffff;
}

// ---------------- K2: per-(b,g) top-k assignment ----------------
__global__ void k_assign(const float* __restrict__ labels)
{
    int g = blockIdx.x, b = blockIdx.y;
    const float* lb = labels + (b*GG + g)*5;
    float l0 = lb[0], gx = lb[1], gy = lb[2], gw = lb[3], gh = lb[4];
    if (!(((((l0+gx)+gy)+gw)+gh) > 0.f)) return;   // invalid gt: matching row all false

    float gtlx = gx-0.5f*gw, gtly = gy-0.5f*gh, gbrx = gx+0.5f*gw, gbry = gy+0.5f*gh;
    float areag = gw*gh;

    int tid = threadIdx.x, lane = tid & 31, wrp = tid >> 5;
    int base = b * AA;

    // per-thread top-10s (register resident; constant-indexed only)
    float tv[10]; ull ck[10];
    #pragma unroll
    for (int j = 0; j < 10; j++){ tv[j] = -1.f; ck[j] = ~0ull; }

    for (int a = tid; a < AA; a += 256){
        float4 p   = g_bbox[base + a];
        float objc = g_objc[base + a];
        bool  fga  = g_fga[base + a] != 0;
        float xc, yc, st; anchor_geom(a, xc, yc, st);

        float ib = min4f(xc-gtlx, gbrx-xc, yc-gtly, gbry-yc);
        float r  = 2.5f * st;
        float ic = min4f(xc-(gx-r), (gx+r)-xc, yc-(gy-r), (gy+r)-yc);
        bool inb = (ib > 0.f) && (ic > 0.f);

        float tlx = fmaxf(gtlx, p.x-0.5f*p.z), tly = fmaxf(gtly, p.y-0.5f*p.w);
        float brx = fminf(gbrx, p.x+0.5f*p.z), bry = fminf(gbry, p.y+0.5f*p.w);
        float ai  = ((tlx < brx) && (tly < bry)) ? (brx-tlx)*(bry-tly) : 0.f;
        float iou = ai / ((areag + p.z*p.w - ai) + 1e-16f);

        float cost = ((objc + 3.f*(-__logf(iou + 1e-8f))) + (inb ? 0.f : 1e5f)) + (fga ? 0.f : 1e7f);
        float im   = fga ? iou : 0.f;

        if (im > tv[9]){
            float x = im;
            #pragma unroll
            for (int j = 0; j < 10; j++){ if (x > tv[j]){ float tt = tv[j]; tv[j] = x; x = tt; } }
        }
        ull key = ((ull)fkey(cost) << 32) | (unsigned)a;   // idx tie-break == stable argsort
        if (key < ck[9]){
            ull x = key;
            #pragma unroll
            for (int j = 0; j < 10; j++){ if (x < ck[j]){ ull tt = ck[j]; ck[j] = x; x = tt; } }
        }
    }

    // dump to smem (dynamic indexing happens in smem, not lmem)
    __shared__ float s_tv[10*256];
    __shared__ ull   s_ckl[10*256];
    __shared__ float s_iou[8][10];
    __shared__ ull   s_ck[8][10];
    #pragma unroll
    for (int j = 0; j < 10; j++){ s_tv[j*256 + tid] = tv[j]; s_ckl[j*256 + tid] = ck[j]; }
    __syncwarp();

    // warp-level extraction: 10 rounds of warp max/min over list heads
    {
        int p = 0;
        for (int rd = 0; rd < 10; rd++){
            float hv = (p < 10) ? s_tv[p*256 + tid] : -2.f;
            float m = hv;
            #pragma unroll
            for (int o = 16; o; o >>= 1) m = fmaxf(m, __shfl_xor_sync(0xffffffffu, m, o));
            unsigned bal = __ballot_sync(0xffffffffu, hv == m);
            if (lane == (__ffs(bal) - 1)) p++;
            if (lane == 0) s_iou[wrp][rd] = m;
        }
    }
    {
        int p = 0;
        for (int rd = 0; rd < 10; rd++){
            ull hv = (p < 10) ? s_ckl[p*256 + tid] : ~0ull;
            ull m = hv;
            #pragma unroll
            for (int o = 16; o; o >>= 1){ ull v = __shfl_xor_sync(0xffffffffu, m, o); if (v < m) m = v; }
            unsigned bal = __ballot_sync(0xffffffffu, hv == m);
            if (lane == (__ffs(bal) - 1)) p++;
            if (lane == 0) s_ck[wrp][rd] = m;
        }
    }
    __syncthreads();

    if (tid == 0){
        // merge 8 sorted iou lists -> sum of top-10 (descending order, like jax top_k then sum)
        int hp[8] = {0,0,0,0,0,0,0,0};
        float sum = 0.f;
        for (int rd = 0; rd < 10; rd++){
            float best = -3.f; int bi = 0;
            #pragma unroll
            for (int w = 0; w < 8; w++){
                float v = (hp[w] < 10) ? s_iou[w][hp[w]] : -3.f;
                if (v > best){ best = v; bi = w; }
            }
            hp[bi]++; sum += best;
        }
        int dynk = (int)sum;            // trunc, matches astype(int32)
        if (dynk < 1) dynk = 1;
        if (dynk > 10) dynk = 10;

        int cp[8] = {0,0,0,0,0,0,0,0};
        for (int i = 0; i < dynk; i++){
            ull best = ~0ull; int bi = 0;
            #pragma unroll
            for (int w = 0; w < 8; w++){
                ull v = (cp[w] < 10) ? s_ck[w][cp[w]] : ~0ull;
                if (v < best){ best = v; bi = w; }
            }
            cp[bi]++;
            int aidx = (int)(best & 0xffffffffull);
            atomicAdd(&g_nmatch[base + aidx], 1);
            atomicMin(&g_ming[base + aidx], g);
        }
    }
}

// ---------------- K3: conflict resolution + loss partials ----------------
__global__ void k_resolve(const float* __restrict__ labels)
{
    int t = blockIdx.x * 256 + threadIdx.x;
    int b = t / AA, a = t - b * AA;

    float4 p = g_bbox[t];
    float ol = g_obj[t];
    int  nm  = g_nmatch[t];
    float sp = softplus_f(ol);

    bool fg = false; int mg = 0;
    if (nm == 1){ fg = true; mg = g_ming[t]; }
    else if (nm > 1){
        // best_gt = argmin_g cost(g, a) over ALL 100 gts (first index on ties)
        float objc = g_objc[t];
        bool  fga  = g_fga[t] != 0;
        float xc, yc, st; anchor_geom(a, xc, yc, st);
        float r = 2.5f * st;
        float ptlx = p.x-0.5f*p.z, ptly = p.y-0.5f*p.w, pbrx = p.x+0.5f*p.z, pbry = p.y+0.5f*p.w;
        float pa = p.z*p.w;
        const float* lb = labels + b*GG*5;
        float best = 3.4e38f; int bi = 0;
        for (int g = 0; g < GG; g++){
            float l0 = lb[g*5], gx = lb[g*5+1], gy = lb[g*5+2], gw = lb[g*5+3], gh = lb[g*5+4];
            bool gv = (((((l0+gx)+gy)+gw)+gh) > 0.f);
            float gtlx = gx-0.5f*gw, gtly = gy-0.5f*gh, gbrx = gx+0.5f*gw, gbry = gy+0.5f*gh;
            float ib = min4f(xc-gtlx, gbrx-xc, yc-gtly, gbry-yc);
            float ic = min4f(xc-(gx-r), (gx+r)-xc, yc-(gy-r), (gy+r)-yc);
            bool inb = (ib > 0.f) && (ic > 0.f);
            float tlx = fmaxf(gtlx, ptlx), tly = fmaxf(gtly, ptly);
            float brx = fminf(gbrx, pbrx), bry = fminf(gbry, pbry);
            float ai  = ((tlx < brx) && (tly < bry)) ? (brx-tlx)*(bry-tly) : 0.f;
            float iou = ai / ((gw*gh + pa - ai) + 1e-16f);
            float cost = ((objc + 3.f*(-__logf(iou + 1e-8f))) + (inb ? 0.f : 1e5f)) + ((gv && fga) ? 0.f : 1e7f);
            if (cost < best){ best = cost; bi = g; }
        }
        mg = bi;
        const float* l = lb + bi*5;
        fg = (((((l[0]+l[1])+l[2])+l[3])+l[4]) > 0.f);   // resolved requires gt_valid[best_gt]
    }

    float li = 0.f, of = 0.f, cnt = 0.f;
    if (fg){
        const float* l = labels + (b*GG + mg)*5;
        float gx = l[1], gy = l[2], gw = l[3], gh = l[4];
        float tlx = fmaxf(p.x-0.5f*p.z, gx-0.5f*gw), tly = fmaxf(p.y-0.5f*p.w, gy-0.5f*gh);
        float brx = fminf(p.x+0.5f*p.z, gx+0.5f*gw), bry = fminf(p.y+0.5f*p.w, gy+0.5f*gh);
        float ai  = ((tlx < brx) && (tly < bry)) ? (brx-tlx)*(bry-tly) : 0.f;
        float iou = ai / ((p.z*p.w + gw*gh - ai) + 1e-16f);
        li = 1.f - iou*iou;
        of = ol;
        cnt = 1.f;
    }

    // deterministic block reduction into fixed partial slots
    __shared__ double sm[256];
    double vals[4] = { (double)sp, (double)of, (double)li, (double)cnt };
    for (int q = 0; q < 4; q++){
        sm[threadIdx.x] = vals[q];
        __syncthreads();
        for (int s = 128; s > 0; s >>= 1){
            if (threadIdx.x < s) sm[threadIdx.x] += sm[threadIdx.x + s];
            __syncthreads();
        }
        if (threadIdx.x == 0) g_part[blockIdx.x*4 + q] = sm[0];
        __syncthreads();
    }
}

// ---------------- K4: final reduction -> 5 outputs ----------------
__global__ void k_final(const float* __restrict__ labels, float* __restrict__ out)
{
    __shared__ double sm[256];
    double acc[4] = {0,0,0,0};
    for (int i = threadIdx.x; i < NBLK1; i += 256){
        acc[0] += g_part[i*4+0];
        acc[1] += g_part[i*4+1];
        acc[2] += g_part[i*4+2];
        acc[3] += g_part[i*4+3];
    }
    double ng = 0.0;
    for (int i = threadIdx.x; i < BB*GG; i += 256){
        const float* l = labels + i*5;
        if ((((((l[0]+l[1])+l[2])+l[3])+l[4])) > 0.f) ng += 1.0;
    }
    double accs[5] = { acc[0], acc[1], acc[2], acc[3], ng };
    double r[5];
    for (int q = 0; q < 5; q++){
        sm[threadIdx.x] = accs[q];
        __syncthreads();
        for (int s = 128; s > 0; s >>= 1){
            if (threadIdx.x < s) sm[threadIdx.x] += sm[threadIdx.x + s];
            __syncthreads();
        }
        r[q] = sm[0];
        __syncthreads();
    }
    if (threadIdx.x == 0){
        float num_fg  = fmaxf((float)r[3], 1.f);
        float num_gts = fmaxf((float)r[4], 1.f);
        float loss_iou = (float)r[2] / num_fg;
        float loss_obj = (float)(r[0] - r[1]) / num_fg;   // sum(softplus(o)) - sum(o * fg)
        out[0] = 5.f*loss_iou + loss_obj;
        out[1] = 5.f*loss_iou;
        out[2] = loss_obj;
        out[3] = 0.f;
        out[4] = num_fg / num_gts;
    }
}

// ---------------- launch ----------------
extern "C" void kernel_launch(void* const* d_in, const int* in_sizes, int n_in,
                              void* d_out, int out_size)
{
    const float *reg0, *reg1, *reg2, *obj0, *obj1, *obj2, *labels;
    if (in_sizes[1] == in_sizes[2]){
        // dict-insertion order: reg0, obj0, reg1, obj1, reg2, obj2, labels
        reg0 = (const float*)d_in[0]; obj0 = (const float*)d_in[1];
        reg1 = (const float*)d_in[2]; obj1 = (const float*)d_in[3];
        reg2 = (const float*)d_in[4]; obj2 = (const float*)d_in[5];
    } else {
        // signature order: reg0, reg1, reg2, obj0, obj1, obj2, labels
        reg0 = (const float*)d_in[0]; reg1 = (const float*)d_in[1]; reg2 = (const float*)d_in[2];
        obj0 = (const float*)d_in[3]; obj1 = (const float*)d_in[4]; obj2 = (const float*)d_in[5];
    }
    labels = (const float*)d_in[6];

    k_decode <<<NBLK1, 256>>>(reg0, obj0, reg1, obj1, reg2, obj2, labels);
    k_assign <<<dim3(GG, BB), 256>>>(labels);
    k_resolve<<<NBLK1, 256>>>(labels);
    k_final  <<<1, 256>>>(labels, (float*)d_out);
}